// round 1
// baseline (speedup 1.0000x reference)
#include <cuda_runtime.h>
#include <math.h>

#define TT   32
#define NN   20000
#define FF   128
#define HH   128
#define CC   10
#define ST   72              // samples per block
#define NTH  384             // threads per block
#define WSS  132             // padded row stride (floats) for transposed weight tile
#define LN_EPS 1e-5f
#define NBLK ((NN + ST - 1) / ST)   // 278 blocks -> ~2 waves on 148 SMs

// Shared layout (floats):
//   Wc   : 256 x WSS   (k-major [W_ih | W_hh], Wc[k][j])
//   xbuf : ST x 128    (current X[t] tile)
//   hbuf : ST x 128    (current hidden state, pre-LN post-ReLU)
//   dwsh : 10 x 128, bcs/gsh/bsh/awsh : 128 each, dbsh : 16, absh : 4
#define SMEM_FLOATS (256*WSS + 2*ST*HH + CC*HH + 4*128 + 16 + 4)

__device__ __forceinline__ void gemm128(float acc[3][8],
                                        const float* __restrict__ buf,
                                        const float* __restrict__ wbase,
                                        int sg, int ja, int jb)
{
    const float* b0 = buf + (sg * 3 + 0) * HH;
    const float* b1 = b0 + HH;
    const float* b2 = b1 + HH;
    const float* wp = wbase;
    #pragma unroll 2
    for (int k = 0; k < 128; k += 4) {
        float xr0[4], xr1[4], xr2[4];
        *(float4*)xr0 = *(const float4*)(b0 + k);
        *(float4*)xr1 = *(const float4*)(b1 + k);
        *(float4*)xr2 = *(const float4*)(b2 + k);
        #pragma unroll
        for (int kk = 0; kk < 4; ++kk) {
            float wr[8];
            *(float4*)(wr)     = *(const float4*)(wp + kk * WSS + ja);
            *(float4*)(wr + 4) = *(const float4*)(wp + kk * WSS + jb);
            #pragma unroll
            for (int u = 0; u < 8; ++u) {
                acc[0][u] = fmaf(xr0[kk], wr[u], acc[0][u]);
                acc[1][u] = fmaf(xr1[kk], wr[u], acc[1][u]);
                acc[2][u] = fmaf(xr2[kk], wr[u], acc[2][u]);
            }
        }
        wp += 4 * WSS;
    }
}

__global__ void __launch_bounds__(NTH, 1)
grn_fused_kernel(const float* __restrict__ X,
                 const float* __restrict__ Wih,
                 const float* __restrict__ Whh,
                 const float* __restrict__ bih,
                 const float* __restrict__ bhh,
                 const float* __restrict__ lng,
                 const float* __restrict__ lnb,
                 const float* __restrict__ aW,
                 const float* __restrict__ aB,
                 const float* __restrict__ dW,
                 const float* __restrict__ dB,
                 float* __restrict__ out)
{
    extern __shared__ float sm[];
    float* Wc   = sm;
    float* xbuf = Wc + 256 * WSS;
    float* hbuf = xbuf + ST * HH;
    float* dwsh = hbuf + ST * HH;
    float* bcs  = dwsh + CC * HH;
    float* gsh  = bcs + 128;
    float* bsh  = gsh + 128;
    float* awsh = bsh + 128;
    float* dbsh = awsh + 128;
    float* absh = dbsh + 16;

    const int tid = threadIdx.x;
    const int sg  = tid >> 4;        // 0..23  (sample group: 3 samples each)
    const int jg  = tid & 15;        // 0..15  (j group)
    const int ja  = jg * 4;          // j-tile half A: [ja, ja+4)
    const int jb  = 64 + jg * 4;     // j-tile half B: [jb, jb+4)
    const int n0  = blockIdx.x * ST;

    // ---- Stage weights (transposed k-major) and params ----
    for (int e = tid; e < 128 * 128; e += NTH) {
        int j = e >> 7, k = e & 127;
        Wc[k * WSS + j]         = Wih[e];
        Wc[(k + 128) * WSS + j] = Whh[e];
    }
    if (tid < 128) {
        bcs[tid]  = bih[tid] + bhh[tid];
        gsh[tid]  = lng[tid];
        bsh[tid]  = lnb[tid];
        awsh[tid] = aW[tid];
    }
    for (int e = tid; e < CC * HH; e += NTH) dwsh[e] = dW[e];
    if (tid < CC) dbsh[tid] = dB[tid];
    if (tid == 0) absh[0] = aB[0];

    // ---- Stage X[0] tile ----
    for (int e = tid; e < ST * 32; e += NTH) {
        int row = e >> 5, c4 = (e & 31) * 4;
        int n = n0 + row; n = (n < NN) ? n : (NN - 1);
        *(float4*)(xbuf + row * HH + c4) = *(const float4*)(X + (size_t)n * FF + c4);
    }
    __syncthreads();

    // ---- Per-thread constants ----
    float greg[8], breg[8], awreg[8], dbreg[CC];
    *(float4*)(greg)     = *(const float4*)(gsh + ja);
    *(float4*)(greg + 4) = *(const float4*)(gsh + jb);
    *(float4*)(breg)     = *(const float4*)(bsh + ja);
    *(float4*)(breg + 4) = *(const float4*)(bsh + jb);
    *(float4*)(awreg)    = *(const float4*)(awsh + ja);
    *(float4*)(awreg + 4)= *(const float4*)(awsh + jb);
    #pragma unroll
    for (int c = 0; c < CC; ++c) dbreg[c] = dbsh[c];
    const float ab_s = absh[0];

    // ---- h0 = X[0] @ W_ih^T + b_ih + b_hh   (no ReLU) ----
    {
        float acc[3][8];
        float br[8];
        *(float4*)(br)     = *(const float4*)(bcs + ja);
        *(float4*)(br + 4) = *(const float4*)(bcs + jb);
        #pragma unroll
        for (int i = 0; i < 3; ++i)
            #pragma unroll
            for (int u = 0; u < 8; ++u) acc[i][u] = br[u];
        gemm128(acc, xbuf, Wc, sg, ja, jb);
        #pragma unroll
        for (int i = 0; i < 3; ++i) {
            float* hp = hbuf + (sg * 3 + i) * HH;
            *(float4*)(hp + ja) = make_float4(acc[i][0], acc[i][1], acc[i][2], acc[i][3]);
            *(float4*)(hp + jb) = make_float4(acc[i][4], acc[i][5], acc[i][6], acc[i][7]);
        }
    }

    // ---- Online-softmax state ----
    float m_[3], l_[3], oacc[3][CC];
    #pragma unroll
    for (int i = 0; i < 3; ++i) {
        m_[i] = -3.0e38f; l_[i] = 0.f;
        #pragma unroll
        for (int c = 0; c < CC; ++c) oacc[i][c] = 0.f;
    }

    // ---- Time loop ----
    for (int t = 0; t < TT; ++t) {
        if (t > 0) {
            __syncthreads();   // prior hbuf writes done; prior xbuf reads done
            const float* Xt = X + (size_t)t * NN * FF;
            for (int e = tid; e < ST * 32; e += NTH) {
                int row = e >> 5, c4 = (e & 31) * 4;
                int n = n0 + row; n = (n < NN) ? n : (NN - 1);
                *(float4*)(xbuf + row * HH + c4) =
                    *(const float4*)(Xt + (size_t)n * FF + c4);
            }
        }
        __syncthreads();

        // h_new = ReLU( x@Wih^T + h@Whh^T + (b_ih + b_hh) )
        float acc[3][8];
        {
            float br[8];
            *(float4*)(br)     = *(const float4*)(bcs + ja);
            *(float4*)(br + 4) = *(const float4*)(bcs + jb);
            #pragma unroll
            for (int i = 0; i < 3; ++i)
                #pragma unroll
                for (int u = 0; u < 8; ++u) acc[i][u] = br[u];
        }
        gemm128(acc, xbuf, Wc,             sg, ja, jb);
        gemm128(acc, hbuf, Wc + 128 * WSS, sg, ja, jb);

        // ReLU + LN partial stats
        float sum[3], sq[3];
        #pragma unroll
        for (int i = 0; i < 3; ++i) {
            float s_ = 0.f, q_ = 0.f;
            #pragma unroll
            for (int u = 0; u < 8; ++u) {
                float v = fmaxf(acc[i][u], 0.f);
                acc[i][u] = v; s_ += v; q_ = fmaf(v, v, q_);
            }
            sum[i] = s_; sq[i] = q_;
        }

        __syncthreads();   // all hbuf reads (GEMM) done before overwrite
        #pragma unroll
        for (int i = 0; i < 3; ++i) {
            float* hp = hbuf + (sg * 3 + i) * HH;
            *(float4*)(hp + ja) = make_float4(acc[i][0], acc[i][1], acc[i][2], acc[i][3]);
            *(float4*)(hp + jb) = make_float4(acc[i][4], acc[i][5], acc[i][6], acc[i][7]);
        }

        // LayerNorm (16-lane butterfly reductions; jg lanes of a sample share a half-warp)
        #pragma unroll
        for (int i = 0; i < 3; ++i) {
            float s_ = sum[i], q_ = sq[i];
            #pragma unroll
            for (int d = 8; d; d >>= 1) {
                s_ += __shfl_xor_sync(0xffffffffu, s_, d);
                q_ += __shfl_xor_sync(0xffffffffu, q_, d);
            }
            float mu   = s_ * (1.f / 128.f);
            float var  = q_ * (1.f / 128.f) - mu * mu;
            float rstd = rsqrtf(var + LN_EPS);
            #pragma unroll
            for (int u = 0; u < 8; ++u)
                acc[i][u] = (acc[i][u] - mu) * rstd * greg[u] + breg[u];
        }

        // attention logit
        float lg[3];
        #pragma unroll
        for (int i = 0; i < 3; ++i) {
            float p = 0.f;
            #pragma unroll
            for (int u = 0; u < 8; ++u) p = fmaf(awreg[u], acc[i][u], p);
            #pragma unroll
            for (int d = 8; d; d >>= 1) p += __shfl_xor_sync(0xffffffffu, p, d);
            lg[i] = p + ab_s;
        }

        // online-softmax rescale factors
        float ps[3], scb[3];
        #pragma unroll
        for (int i = 0; i < 3; ++i) {
            float mn = fmaxf(m_[i], lg[i]);
            float sc = __expf(m_[i] - mn);
            float p  = __expf(lg[i] - mn);
            m_[i] = mn;
            l_[i] = l_[i] * sc + p;
            ps[i] = p; scb[i] = sc;
        }

        // dense projection + weighted accumulate
        #pragma unroll
        for (int c = 0; c < CC; ++c) {
            float wr[8];
            *(float4*)(wr)     = *(const float4*)(dwsh + c * HH + ja);
            *(float4*)(wr + 4) = *(const float4*)(dwsh + c * HH + jb);
            #pragma unroll
            for (int i = 0; i < 3; ++i) {
                float p = 0.f;
                #pragma unroll
                for (int u = 0; u < 8; ++u) p = fmaf(wr[u], acc[i][u], p);
                #pragma unroll
                for (int d = 8; d; d >>= 1) p += __shfl_xor_sync(0xffffffffu, p, d);
                oacc[i][c] = oacc[i][c] * scb[i] + ps[i] * (p + dbreg[c]);
            }
        }
    }

    // ---- Epilogue: out[n][c] = oacc / l ----
    if (jg == 0) {
        #pragma unroll
        for (int i = 0; i < 3; ++i) {
            int n = n0 + sg * 3 + i;
            if (n < NN) {
                float inv = 1.f / l_[i];
                #pragma unroll
                for (int c = 0; c < CC; ++c) out[n * CC + c] = oacc[i][c] * inv;
            }
        }
    }
}

extern "C" void kernel_launch(void* const* d_in, const int* in_sizes, int n_in,
                              void* d_out, int out_size)
{
    (void)in_sizes; (void)n_in; (void)out_size;
    const float* X    = (const float*)d_in[0];
    const float* Wih  = (const float*)d_in[1];
    const float* Whh  = (const float*)d_in[2];
    const float* bih  = (const float*)d_in[3];
    const float* bhh  = (const float*)d_in[4];
    const float* lng  = (const float*)d_in[5];
    const float* lnb  = (const float*)d_in[6];
    const float* aW   = (const float*)d_in[7];
    const float* aB   = (const float*)d_in[8];
    const float* dW   = (const float*)d_in[9];
    const float* dB   = (const float*)d_in[10];
    float* out = (float*)d_out;

    const int smem_bytes = SMEM_FLOATS * (int)sizeof(float);   // ~216 KB
    cudaFuncSetAttribute(grn_fused_kernel,
                         cudaFuncAttributeMaxDynamicSharedMemorySize, smem_bytes);
    grn_fused_kernel<<<NBLK, NTH, smem_bytes>>>(X, Wih, Whh, bih, bhh, lng, lnb,
                                                aW, aB, dW, dB, out);
}

// round 2
// speedup vs baseline: 1.0770x; 1.0770x over previous
#include <cuda_runtime.h>
#include <math.h>

#define TT   32
#define NN   20000
#define FF   128
#define HH   128
#define CC   10
#define ST   72              // samples per block
#define NTH  384             // threads per block
#define WSS  132             // padded row stride (floats); 132*4=528 B keeps 16B alignment
#define LN_EPS 1e-5f
#define NBLK ((NN + ST - 1) / ST)   // 278 blocks -> 2 waves on 148 SMs

typedef unsigned long long u64;

// Shared layout (floats):
//   Wc   : 256 x WSS   (k-major [W_ih | W_hh], Wc[k][j])
//   xbuf : ST x 128    (current X[t] tile)
//   hbuf : ST x 128    (current hidden state, pre-LN post-ReLU)
//   dwsh : 10 x 128, bcs/gsh/bsh/awsh : 128 each, dbsh : 16, absh : 4
#define SMEM_FLOATS (256*WSS + 2*ST*HH + CC*HH + 4*128 + 16 + 4)

// ---- packed f32x2 helpers (Blackwell FFMA2 path) ----
__device__ __forceinline__ u64 pk2(float x) {            // {x, x}
    u64 r; asm("mov.b64 %0, {%1,%1};" : "=l"(r) : "f"(x)); return r;
}
__device__ __forceinline__ u64 pkp(float x, float y) {   // {x, y}
    u64 r; asm("mov.b64 %0, {%1,%2};" : "=l"(r) : "f"(x), "f"(y)); return r;
}
__device__ __forceinline__ float2 up2(u64 v) {
    float2 f; asm("mov.b64 {%0,%1}, %2;" : "=f"(f.x), "=f"(f.y) : "l"(v)); return f;
}
__device__ __forceinline__ void ffma2(u64& d, u64 a, u64 b) {
    asm("fma.rn.f32x2 %0, %1, %2, %0;" : "+l"(d) : "l"(a), "l"(b));
}

// 3-sample x 8-col register tile GEMM over k=0..127, packed f32x2 (j pairs).
__device__ __forceinline__ void gemm2(u64 acc[3][4],
                                      const float* __restrict__ buf,
                                      const float* __restrict__ wbase,
                                      int sg, int ja, int jb)
{
    const float* b0 = buf + (sg * 3 + 0) * HH;
    const float* b1 = b0 + HH;
    const float* b2 = b1 + HH;
    const float* wp = wbase;
    #pragma unroll 2
    for (int k = 0; k < 128; k += 4) {
        float4 x0 = *(const float4*)(b0 + k);
        float4 x1 = *(const float4*)(b1 + k);
        float4 x2 = *(const float4*)(b2 + k);
        const float* xs0 = (const float*)&x0;
        const float* xs1 = (const float*)&x1;
        const float* xs2 = (const float*)&x2;
        #pragma unroll
        for (int kk = 0; kk < 4; ++kk) {
            ulonglong2 wa = *(const ulonglong2*)(wp + kk * WSS + ja);
            ulonglong2 wb = *(const ulonglong2*)(wp + kk * WSS + jb);
            u64 d0 = pk2(xs0[kk]);
            u64 d1 = pk2(xs1[kk]);
            u64 d2 = pk2(xs2[kk]);
            ffma2(acc[0][0], d0, wa.x); ffma2(acc[0][1], d0, wa.y);
            ffma2(acc[0][2], d0, wb.x); ffma2(acc[0][3], d0, wb.y);
            ffma2(acc[1][0], d1, wa.x); ffma2(acc[1][1], d1, wa.y);
            ffma2(acc[1][2], d1, wb.x); ffma2(acc[1][3], d1, wb.y);
            ffma2(acc[2][0], d2, wa.x); ffma2(acc[2][1], d2, wa.y);
            ffma2(acc[2][2], d2, wb.x); ffma2(acc[2][3], d2, wb.y);
        }
        wp += 4 * WSS;
    }
}

__global__ void __launch_bounds__(NTH, 1)
grn_fused_kernel(const float* __restrict__ X,
                 const float* __restrict__ Wih,
                 const float* __restrict__ Whh,
                 const float* __restrict__ bih,
                 const float* __restrict__ bhh,
                 const float* __restrict__ lng,
                 const float* __restrict__ lnb,
                 const float* __restrict__ aW,
                 const float* __restrict__ aB,
                 const float* __restrict__ dW,
                 const float* __restrict__ dB,
                 float* __restrict__ out)
{
    extern __shared__ float sm[];
    float* Wc   = sm;
    float* xbuf = Wc + 256 * WSS;
    float* hbuf = xbuf + ST * HH;
    float* dwsh = hbuf + ST * HH;
    float* bcs  = dwsh + CC * HH;
    float* gsh  = bcs + 128;
    float* bsh  = gsh + 128;
    float* awsh = bsh + 128;
    float* dbsh = awsh + 128;
    float* absh = dbsh + 16;

    const int tid = threadIdx.x;
    const int sg  = tid >> 4;        // 0..23  (sample group: 3 samples each)
    const int jg  = tid & 15;        // 0..15  (j group)
    const int ja  = jg * 4;
    const int jb  = 64 + jg * 4;
    const int n0  = blockIdx.x * ST;

    // ---- Stage weights (transposed k-major) and params ----
    for (int e = tid; e < 128 * 128; e += NTH) {
        int j = e >> 7, k = e & 127;
        Wc[k * WSS + j]         = Wih[e];
        Wc[(k + 128) * WSS + j] = Whh[e];
    }
    if (tid < 128) {
        bcs[tid]  = bih[tid] + bhh[tid];
        gsh[tid]  = lng[tid];
        bsh[tid]  = lnb[tid];
        awsh[tid] = aW[tid];
    }
    for (int e = tid; e < CC * HH; e += NTH) dwsh[e] = dW[e];
    if (tid < CC) dbsh[tid] = dB[tid];
    if (tid == 0) absh[0] = aB[0];

    // ---- Stage X[0] tile ----
    for (int e = tid; e < ST * 32; e += NTH) {
        int row = e >> 5, c4 = (e & 31) * 4;
        int n = n0 + row; n = (n < NN) ? n : (NN - 1);
        *(float4*)(xbuf + row * HH + c4) = *(const float4*)(X + (size_t)n * FF + c4);
    }
    __syncthreads();

    // ---- Per-thread constants ----
    float greg[8], breg[8], dbreg[CC];
    u64 awp[4], bp[4];
    *(float4*)(greg)     = *(const float4*)(gsh + ja);
    *(float4*)(greg + 4) = *(const float4*)(gsh + jb);
    *(float4*)(breg)     = *(const float4*)(bsh + ja);
    *(float4*)(breg + 4) = *(const float4*)(bsh + jb);
    {
        float aw[8];
        *(float4*)(aw)     = *(const float4*)(awsh + ja);
        *(float4*)(aw + 4) = *(const float4*)(awsh + jb);
        #pragma unroll
        for (int q = 0; q < 4; ++q) awp[q] = pkp(aw[2 * q], aw[2 * q + 1]);
        float br[8];
        *(float4*)(br)     = *(const float4*)(bcs + ja);
        *(float4*)(br + 4) = *(const float4*)(bcs + jb);
        #pragma unroll
        for (int q = 0; q < 4; ++q) bp[q] = pkp(br[2 * q], br[2 * q + 1]);
    }
    #pragma unroll
    for (int c = 0; c < CC; ++c) dbreg[c] = dbsh[c];
    const float ab_s = absh[0];

    // ---- h0 = X[0] @ W_ih^T + b_ih + b_hh   (no ReLU) ----
    {
        u64 acc[3][4];
        #pragma unroll
        for (int i = 0; i < 3; ++i)
            #pragma unroll
            for (int q = 0; q < 4; ++q) acc[i][q] = bp[q];
        gemm2(acc, xbuf, Wc, sg, ja, jb);
        #pragma unroll
        for (int i = 0; i < 3; ++i) {
            float2 v0 = up2(acc[i][0]), v1 = up2(acc[i][1]);
            float2 v2 = up2(acc[i][2]), v3 = up2(acc[i][3]);
            float* hp = hbuf + (sg * 3 + i) * HH;
            *(float4*)(hp + ja) = make_float4(v0.x, v0.y, v1.x, v1.y);
            *(float4*)(hp + jb) = make_float4(v2.x, v2.y, v3.x, v3.y);
        }
    }

    // ---- Online-softmax state ----
    float m_[3], l_[3], oacc[3][CC];
    #pragma unroll
    for (int i = 0; i < 3; ++i) {
        m_[i] = -3.0e38f; l_[i] = 0.f;
        #pragma unroll
        for (int c = 0; c < CC; ++c) oacc[i][c] = 0.f;
    }

    // ---- Time loop ----
    for (int t = 0; t < TT; ++t) {
        __syncthreads();   // xbuf/hbuf stores visible before GEMM reads

        // h_new = ReLU( x@Wih^T + h@Whh^T + (b_ih + b_hh) )
        u64 acc[3][4];
        #pragma unroll
        for (int i = 0; i < 3; ++i)
            #pragma unroll
            for (int q = 0; q < 4; ++q) acc[i][q] = bp[q];
        gemm2(acc, xbuf, Wc,             sg, ja, jb);
        gemm2(acc, hbuf, Wc + 128 * WSS, sg, ja, jb);

        // unpack + ReLU + LN partial stats
        float av[3][8], sum[3], sq[3];
        #pragma unroll
        for (int i = 0; i < 3; ++i) {
            float2 v0 = up2(acc[i][0]), v1 = up2(acc[i][1]);
            float2 v2 = up2(acc[i][2]), v3 = up2(acc[i][3]);
            av[i][0] = v0.x; av[i][1] = v0.y; av[i][2] = v1.x; av[i][3] = v1.y;
            av[i][4] = v2.x; av[i][5] = v2.y; av[i][6] = v3.x; av[i][7] = v3.y;
            float s_ = 0.f, q_ = 0.f;
            #pragma unroll
            for (int u = 0; u < 8; ++u) {
                float v = fmaxf(av[i][u], 0.f);
                av[i][u] = v; s_ += v; q_ = fmaf(v, v, q_);
            }
            sum[i] = s_; sq[i] = q_;
        }

        __syncthreads();   // all xbuf/hbuf reads done before overwrite

        #pragma unroll
        for (int i = 0; i < 3; ++i) {
            float* hp = hbuf + (sg * 3 + i) * HH;
            *(float4*)(hp + ja) = make_float4(av[i][0], av[i][1], av[i][2], av[i][3]);
            *(float4*)(hp + jb) = make_float4(av[i][4], av[i][5], av[i][6], av[i][7]);
        }
        if (t + 1 < TT) {
            const float* Xt = X + (size_t)(t + 1) * NN * FF;
            for (int e = tid; e < ST * 32; e += NTH) {
                int row = e >> 5, c4 = (e & 31) * 4;
                int n = n0 + row; n = (n < NN) ? n : (NN - 1);
                *(float4*)(xbuf + row * HH + c4) =
                    *(const float4*)(Xt + (size_t)n * FF + c4);
            }
        }

        // ---- Epilogue (register-only + read-only dwsh; overlaps X load latency) ----
        u64 lnp[3][4];
        float lg[3];
        #pragma unroll
        for (int i = 0; i < 3; ++i) {
            float s_ = sum[i], q_ = sq[i];
            #pragma unroll
            for (int d = 8; d; d >>= 1) {
                s_ += __shfl_xor_sync(0xffffffffu, s_, d);
                q_ += __shfl_xor_sync(0xffffffffu, q_, d);
            }
            float mu   = s_ * (1.f / 128.f);
            float var  = q_ * (1.f / 128.f) - mu * mu;
            float rstd = rsqrtf(var + LN_EPS);
            float y[8];
            #pragma unroll
            for (int u = 0; u < 8; ++u)
                y[u] = fmaf((av[i][u] - mu) * rstd, greg[u], breg[u]);
            #pragma unroll
            for (int q2 = 0; q2 < 4; ++q2) lnp[i][q2] = pkp(y[2 * q2], y[2 * q2 + 1]);

            // attention logit (packed dot + 16-lane butterfly)
            u64 pa = 0ull;
            #pragma unroll
            for (int q2 = 0; q2 < 4; ++q2) ffma2(pa, awp[q2], lnp[i][q2]);
            float2 pf = up2(pa);
            float p = pf.x + pf.y;
            #pragma unroll
            for (int d = 8; d; d >>= 1) p += __shfl_xor_sync(0xffffffffu, p, d);
            lg[i] = p + ab_s;
        }

        // online-softmax rescale factors
        float ps[3], scb[3];
        #pragma unroll
        for (int i = 0; i < 3; ++i) {
            float mn = fmaxf(m_[i], lg[i]);
            float sc = __expf(m_[i] - mn);
            float p  = __expf(lg[i] - mn);
            m_[i] = mn;
            l_[i] = l_[i] * sc + p;
            ps[i] = p; scb[i] = sc;
        }

        // dense projection + weighted accumulate (packed dots)
        #pragma unroll
        for (int c = 0; c < CC; ++c) {
            ulonglong2 w01 = *(const ulonglong2*)(dwsh + c * HH + ja);
            ulonglong2 w23 = *(const ulonglong2*)(dwsh + c * HH + jb);
            #pragma unroll
            for (int i = 0; i < 3; ++i) {
                u64 pd = 0ull;
                ffma2(pd, w01.x, lnp[i][0]); ffma2(pd, w01.y, lnp[i][1]);
                ffma2(pd, w23.x, lnp[i][2]); ffma2(pd, w23.y, lnp[i][3]);
                float2 pf = up2(pd);
                float p = pf.x + pf.y;
                #pragma unroll
                for (int d = 8; d; d >>= 1) p += __shfl_xor_sync(0xffffffffu, p, d);
                oacc[i][c] = oacc[i][c] * scb[i] + ps[i] * (p + dbreg[c]);
            }
        }
    }

    // ---- Epilogue: out[n][c] = oacc / l ----
    if (jg == 0) {
        #pragma unroll
        for (int i = 0; i < 3; ++i) {
            int n = n0 + sg * 3 + i;
            if (n < NN) {
                float inv = 1.f / l_[i];
                #pragma unroll
                for (int c = 0; c < CC; ++c) out[n * CC + c] = oacc[i][c] * inv;
            }
        }
    }
}

extern "C" void kernel_launch(void* const* d_in, const int* in_sizes, int n_in,
                              void* d_out, int out_size)
{
    (void)in_sizes; (void)n_in; (void)out_size;
    const float* X    = (const float*)d_in[0];
    const float* Wih  = (const float*)d_in[1];
    const float* Whh  = (const float*)d_in[2];
    const float* bih  = (const float*)d_in[3];
    const float* bhh  = (const float*)d_in[4];
    const float* lng  = (const float*)d_in[5];
    const float* lnb  = (const float*)d_in[6];
    const float* aW   = (const float*)d_in[7];
    const float* aB   = (const float*)d_in[8];
    const float* dW   = (const float*)d_in[9];
    const float* dB   = (const float*)d_in[10];
    float* out = (float*)d_out;

    const int smem_bytes = SMEM_FLOATS * (int)sizeof(float);   // ~216 KB
    cudaFuncSetAttribute(grn_fused_kernel,
                         cudaFuncAttributeMaxDynamicSharedMemorySize, smem_bytes);
    grn_fused_kernel<<<NBLK, NTH, smem_bytes>>>(X, Wih, Whh, bih, bhh, lng, lnb,
                                                aW, aB, dW, dB, out);
}